// round 6
// baseline (speedup 1.0000x reference)
#include <cuda_runtime.h>
#include <cuda_fp16.h>

typedef unsigned long long u64;

// ---------------- f32x2 helpers (sm_100+) ----------------
__device__ __forceinline__ u64 pack2(float x) {
    u64 r;
    asm("mov.b64 %0, {%1, %1};" : "=l"(r) : "f"(x));
    return r;
}
__device__ __forceinline__ u64 pack2f(float lo, float hi) {
    u64 r;
    asm("mov.b64 %0, {%1, %2};" : "=l"(r) : "f"(lo), "f"(hi));
    return r;
}
__device__ __forceinline__ void fma2(u64& d, u64 a, u64 b) {
    asm("fma.rn.f32x2 %0, %1, %2, %3;" : "=l"(d) : "l"(a), "l"(b), "l"(d));
}
__device__ __forceinline__ u64 fma2_3(u64 a, u64 b, u64 c) {
    u64 d;
    asm("fma.rn.f32x2 %0, %1, %2, %3;" : "=l"(d) : "l"(a), "l"(b), "l"(c));
    return d;
}
__device__ __forceinline__ u64 mul2_(u64 a, u64 b) {
    u64 d; asm("mul.rn.f32x2 %0, %1, %2;" : "=l"(d) : "l"(a), "l"(b)); return d;
}
__device__ __forceinline__ u64 add2_(u64 a, u64 b) {
    u64 d; asm("add.rn.f32x2 %0, %1, %2;" : "=l"(d) : "l"(a), "l"(b)); return d;
}
__device__ __forceinline__ u64 sub2_(u64 a, u64 b) {
    u64 d; asm("sub.rn.f32x2 %0, %1, %2;" : "=l"(d) : "l"(a), "l"(b)); return d;
}
__device__ __forceinline__ void unpack2(u64 v, float& lo, float& hi) {
    asm("mov.b64 {%0, %1}, %2;" : "=f"(lo), "=f"(hi) : "l"(v));
}

// packed exact elu on a pair
__device__ __forceinline__ u64 elu2(u64 v) {
    float lo, hi; unpack2(v, lo, hi);
    u64 m = pack2f(fminf(lo, 0.f), fminf(hi, 0.f));
    u64 s = mul2_(m, 0x3FB8AA3B3FB8AA3BULL);   // * log2(e)
    float sl, sh; unpack2(s, sl, sh);
    float el, eh;
    asm("ex2.approx.f32 %0, %1;" : "=f"(el) : "f"(sl));
    asm("ex2.approx.f32 %0, %1;" : "=f"(eh) : "f"(sh));
    u64 e = pack2f(el, eh);
    u64 p = sub2_(v, m);
    return add2_(add2_(e, p), 0xBF800000BF800000ULL);
}
__device__ __forceinline__ float elu_f(float x) {
    return fmaxf(x, 0.f) + __expf(fminf(x, 0.f)) - 1.f;
}

// ---------------- parameter block in constant memory ----------------
struct CParams {
    float4 WU[2][150];   // [dir][k*10+j]  k < KTOT<=15, permuted (unit-pair, gate-pair)
    float4 Bias[2][10];
    float4 V[2][20];
    float4 R[2];
    float4 C[2];
};
__constant__ CParams cP;
__device__ CParams g_pack[4];

// ---------------- scratch ----------------
__device__ float g_buf0[524288];
__device__ float g_buf1[65536];
__device__ float g_buf2[8192];

// ---------------- pack kernel: gmem weights -> g_pack[4] (permuted) ----------------
__global__ void pack_kernel(
    const float* w0f, const float* u0f, const float* b0f,
    const float* w0b, const float* u0b, const float* b0b,
    const float* w1f, const float* u1f, const float* b1f,
    const float* w1b, const float* u1b, const float* b1b,
    const float* vF, const float* rF, const float* cF,
    const float* vB, const float* rB, const float* cB)
{
    const int tid = threadIdx.x;
    for (int lv = 0; lv < 4; lv++) {
        CParams* P = &g_pack[lv];
        const int CIN = (lv == 0) ? 5 : 1;
        const int KTOT = CIN + 10;
        const float* wFp = (lv == 0) ? w0f : w1f + (lv - 1) * 40;
        const float* uFp = (lv == 0) ? u0f : u1f + (lv - 1) * 400;
        const float* bFp = (lv == 0) ? b0f : b1f + (lv - 1) * 40;
        const float* wBp = (lv == 0) ? w0b : w1b + (lv - 1) * 40;
        const float* uBp = (lv == 0) ? u0b : u1b + (lv - 1) * 400;
        const float* bBp = (lv == 0) ? b0b : b1b + (lv - 1) * 40;

        for (int i = tid; i < 2 * KTOT * 10; i += blockDim.x) {
            int d = i / (KTOT * 10);
            int r = i - d * (KTOT * 10);
            int k = r / 10;
            int j = r - k * 10;
            const float* W = (k < CIN) ? ((d ? wBp : wFp) + k * 40)
                                       : ((d ? uBp : uFp) + (k - CIN) * 40);
            int mp = j >> 1, gp = j & 1;
            int c0 = (2 * gp) * 10 + 2 * mp;
            int c2 = (2 * gp + 1) * 10 + 2 * mp;
            P->WU[d][k * 10 + j] = make_float4(W[c0], W[c0 + 1], W[c2], W[c2 + 1]);
        }
        for (int i = tid; i < 20; i += blockDim.x) {
            int d = i / 10, j = i % 10;
            const float* B = d ? bBp : bFp;
            int mp = j >> 1, gp = j & 1;
            int c0 = (2 * gp) * 10 + 2 * mp;
            int c2 = (2 * gp + 1) * 10 + 2 * mp;
            P->Bias[d][j] = make_float4(B[c0], B[c0 + 1], B[c2], B[c2 + 1]);
        }
        for (int i = tid; i < 40; i += blockDim.x) {
            int d = i / 20, k = i % 20;
            const float* V = (d ? vB : vF) + lv * 80;
            P->V[d][k] = make_float4(V[k * 4 + 0], V[k * 4 + 1], V[k * 4 + 2], V[k * 4 + 3]);
        }
        if (tid < 2) {
            const float* R = (tid ? rB : rF) + lv * 4;
            const float* C = (tid ? cB : cF) + lv * 4;
            P->R[tid] = make_float4(R[0], R[1], R[2], R[3]);
            P->C[tid] = make_float4(C[0], C[1], C[2], C[3]);
        }
    }
}

// ---------------- LSTM1: one direction (compile-time), two sequences ----------------
template <int CIN, int S, int DIR>
__device__ __forceinline__ void lstm1_run(const float* xs, __half2* hsm2, int sA, int sB)
{
    constexpr int XW = 8 * CIN + 1;
    constexpr int SP = S + 1;
    const float* xA = xs + sA * XW;
    const float* xB = xs + sB * XW;

    u64 hA[5], cA[5], hB[5], cB[5];
#pragma unroll
    for (int m = 0; m < 5; m++) { hA[m] = 0ULL; cA[m] = 0ULL; hB[m] = 0ULL; cB[m] = 0ULL; }

#pragma unroll 1
    for (int s = 0; s < 8; s++) {
        const int t = DIR ? (7 - s) : s;
        u64 aA[20], aB[20];
#pragma unroll
        for (int j = 0; j < 10; j++) {
            ulonglong2 bq = *(const ulonglong2*)&cP.Bias[DIR][j];
            int p = (j >> 1) * 4 + 2 * (j & 1);
            aA[p] = bq.x; aA[p + 1] = bq.y;
            aB[p] = bq.x; aB[p + 1] = bq.y;
        }
#pragma unroll
        for (int k = 0; k < CIN; k++) {
            u64 pA = pack2(xA[t * CIN + k]);
            u64 pB = pack2(xB[t * CIN + k]);
#pragma unroll
            for (int j = 0; j < 10; j++) {
                ulonglong2 wq = *(const ulonglong2*)&cP.WU[DIR][k * 10 + j];
                int p = (j >> 1) * 4 + 2 * (j & 1);
                fma2(aA[p], pA, wq.x);
                fma2(aA[p + 1], pA, wq.y);
                fma2(aB[p], pB, wq.x);
                fma2(aB[p + 1], pB, wq.y);
            }
        }
#pragma unroll
        for (int kp = 0; kp < 5; kp++) {
            float a0, a1, b0, b1;
            unpack2(hA[kp], a0, a1);
            unpack2(hB[kp], b0, b1);
#pragma unroll
            for (int sub = 0; sub < 2; sub++) {
                const int k = kp * 2 + sub;
                u64 pA = pack2(sub ? a1 : a0);
                u64 pB = pack2(sub ? b1 : b0);
#pragma unroll
                for (int j = 0; j < 10; j++) {
                    ulonglong2 wq = *(const ulonglong2*)&cP.WU[DIR][(CIN + k) * 10 + j];
                    int p = (j >> 1) * 4 + 2 * (j & 1);
                    fma2(aA[p], pA, wq.x);
                    fma2(aA[p + 1], pA, wq.y);
                    fma2(aB[p], pB, wq.x);
                    fma2(aB[p + 1], pB, wq.y);
                }
            }
        }
        // gates i,f,g,o packed: c = elu2(f)*c + elu2(i)*elu2(g); h = elu2(o)*elu2(c)
        __half2* hrow = hsm2 + (DIR * 40 + t * 5) * SP;
#pragma unroll
        for (int mp = 0; mp < 5; mp++) {
            {
                u64 ei = elu2(aA[mp * 4 + 0]);
                u64 ef = elu2(aA[mp * 4 + 1]);
                u64 eg = elu2(aA[mp * 4 + 2]);
                u64 eo = elu2(aA[mp * 4 + 3]);
                cA[mp] = fma2_3(ef, cA[mp], mul2_(ei, eg));
                hA[mp] = mul2_(eo, elu2(cA[mp]));
                float l, h; unpack2(hA[mp], l, h);
                hrow[mp * SP + sA] = __floats2half2_rn(l, h);
            }
            {
                u64 ei = elu2(aB[mp * 4 + 0]);
                u64 ef = elu2(aB[mp * 4 + 1]);
                u64 eg = elu2(aB[mp * 4 + 2]);
                u64 eo = elu2(aB[mp * 4 + 3]);
                cB[mp] = fma2_3(ef, cB[mp], mul2_(ei, eg));
                hB[mp] = mul2_(eo, elu2(cB[mp]));
                float l, h; unpack2(hB[mp], l, h);
                hrow[mp * SP + sB] = __floats2half2_rn(l, h);
            }
        }
    }
}

// ---------------- LSTM2 (H=1), one direction (compile-time), two sequences ----------------
template <int S, int DIR>
__device__ __forceinline__ void lstm2_run(const __half2* hsm2, int sA, int sB,
                                          float& outA, float& outB)
{
    constexpr int SP = S + 1;
    const ulonglong2 rq = *(const ulonglong2*)&cP.R[DIR];
    const ulonglong2 cq = *(const ulonglong2*)&cP.C[DIR];

    u64 yA0[8], yA1[8], yB0[8], yB1[8];
#pragma unroll
    for (int t = 0; t < 8; t++) { yA0[t] = cq.x; yA1[t] = cq.y; yB0[t] = cq.x; yB1[t] = cq.y; }

#pragma unroll
    for (int d2 = 0; d2 < 2; d2++) {
#pragma unroll
        for (int up = 0; up < 5; up++) {
            ulonglong2 v0 = *(const ulonglong2*)&cP.V[DIR][d2 * 10 + 2 * up];
            ulonglong2 v1 = *(const ulonglong2*)&cP.V[DIR][d2 * 10 + 2 * up + 1];
#pragma unroll
            for (int t = 0; t < 8; t++) {
                const int row = d2 * 40 + t * 5 + up;
                float2 fa = __half22float2(hsm2[row * SP + sA]);
                float2 fb = __half22float2(hsm2[row * SP + sB]);
                u64 a0 = pack2(fa.x), a1 = pack2(fa.y);
                u64 b0 = pack2(fb.x), b1 = pack2(fb.y);
                fma2(yA0[t], a0, v0.x); fma2(yA1[t], a0, v0.y);
                fma2(yA0[t], a1, v1.x); fma2(yA1[t], a1, v1.y);
                fma2(yB0[t], b0, v0.x); fma2(yB1[t], b0, v0.y);
                fma2(yB0[t], b1, v1.x); fma2(yB1[t], b1, v1.y);
            }
        }
    }

    float hA = 0.f, cA = 0.f, hB = 0.f, cB = 0.f;
#define REC_STEP(T)                                                  \
    {                                                                \
        u64 zA0 = yA0[T], zA1 = yA1[T], zB0 = yB0[T], zB1 = yB1[T];  \
        u64 pa = pack2(hA), pb = pack2(hB);                          \
        fma2(zA0, pa, rq.x); fma2(zA1, pa, rq.y);                    \
        fma2(zB0, pb, rq.x); fma2(zB1, pb, rq.y);                    \
        u64 eA = elu2(zA0);                                          \
        float eiA, efA; unpack2(eA, eiA, efA);                       \
        float zgA, zoA; unpack2(zA1, zgA, zoA);                      \
        cA = efA * cA + eiA * zgA;                                   \
        hA = elu_f(zoA) * cA;                                        \
        u64 eB = elu2(zB0);                                          \
        float eiB, efB; unpack2(eB, eiB, efB);                       \
        float zgB, zoB; unpack2(zB1, zgB, zoB);                      \
        cB = efB * cB + eiB * zgB;                                   \
        hB = elu_f(zoB) * cB;                                        \
    }
    if (DIR == 0) {
        REC_STEP(0) REC_STEP(1) REC_STEP(2) REC_STEP(3)
        REC_STEP(4) REC_STEP(5) REC_STEP(6) REC_STEP(7)
    } else {
        REC_STEP(7) REC_STEP(6) REC_STEP(5) REC_STEP(4)
        REC_STEP(3) REC_STEP(2) REC_STEP(1) REC_STEP(0)
    }
#undef REC_STEP
    outA = hA; outB = hB;
}

__host__ __device__ constexpr int smem_floats(int CIN, int S) {
    return 80 * (S + 1) + S * (8 * CIN + 1);
}

// Warp parity = direction; lane l of warp pair handles seqs (2l, 2l+1).
template <int CIN, int S>
__global__ void __launch_bounds__(S, 6)
agg_kernel(const float* __restrict__ in, float* __restrict__ out)
{
    extern __shared__ float smem[];
    constexpr int XW = 8 * CIN + 1;
    __half2* hsm2 = (__half2*)smem;            // [80][S+1] half2
    float* xs = smem + 80 * (S + 1);           // [S][XW]

    const int tid = threadIdx.x;

    // stage x (coalesced; grids divide exactly)
    {
        long long base = (long long)blockIdx.x * S * (8 * CIN);
        const int total = S * 8 * CIN;
        for (int i = tid; i < total; i += S)
            xs[(i / (8 * CIN)) * XW + (i % (8 * CIN))] = in[base + i];
    }
    __syncthreads();

    const int wid = tid >> 5;
    const int lane = tid & 31;
    const int dir = wid & 1;
    const int sA = (wid >> 1) * 64 + lane * 2;
    const int sB = sA + 1;

    if (dir == 0) lstm1_run<CIN, S, 0>(xs, hsm2, sA, sB);
    else          lstm1_run<CIN, S, 1>(xs, hsm2, sA, sB);
    __syncthreads();

    float h2A, h2B;
    if (dir == 0) lstm2_run<S, 0>(hsm2, sA, sB, h2A, h2B);
    else          lstm2_run<S, 1>(hsm2, sA, sB, h2A, h2B);

    // combine fwd/bwd via smem (reuse xs)
    if (dir == 1) { xs[sA] = h2A; xs[sB] = h2B; }
    __syncthreads();
    if (dir == 0) {
        out[blockIdx.x * S + sA] = 1.f / (1.f + __expf(-0.5f * (h2A + xs[sA])));
        out[blockIdx.x * S + sB] = 1.f / (1.f + __expf(-0.5f * (h2B + xs[sB])));
    }
}

extern "C" void kernel_launch(void* const* d_in, const int* in_sizes, int n_in,
                              void* d_out, int out_size)
{
    const float* x   = (const float*)d_in[0];
    const float* w0f = (const float*)d_in[1];
    const float* u0f = (const float*)d_in[2];
    const float* b0f = (const float*)d_in[3];
    const float* w0b = (const float*)d_in[4];
    const float* u0b = (const float*)d_in[5];
    const float* b0b = (const float*)d_in[6];
    const float* w1f = (const float*)d_in[7];
    const float* u1f = (const float*)d_in[8];
    const float* b1f = (const float*)d_in[9];
    const float* w1b = (const float*)d_in[10];
    const float* u1b = (const float*)d_in[11];
    const float* b1b = (const float*)d_in[12];
    const float* vF  = (const float*)d_in[13];
    const float* rF  = (const float*)d_in[14];
    const float* cF  = (const float*)d_in[15];
    const float* vB  = (const float*)d_in[16];
    const float* rB  = (const float*)d_in[17];
    const float* cB  = (const float*)d_in[18];
    float* out = (float*)d_out;

    float *buf0, *buf1, *buf2;
    cudaGetSymbolAddress((void**)&buf0, g_buf0);
    cudaGetSymbolAddress((void**)&buf1, g_buf1);
    cudaGetSymbolAddress((void**)&buf2, g_buf2);
    CParams* packp;
    cudaGetSymbolAddress((void**)&packp, g_pack);

    // pack all levels' params (permuted) into g_pack
    pack_kernel<<<1, 256>>>(w0f, u0f, b0f, w0b, u0b, b0b,
                            w1f, u1f, b1f, w1b, u1b, b1b,
                            vF, rF, cF, vB, rB, cB);

    const size_t smem5 = (size_t)smem_floats(5, 64) * sizeof(float);
    const size_t smem1 = (size_t)smem_floats(1, 64) * sizeof(float);

    // level 0
    cudaMemcpyToSymbolAsync(cP, packp + 0, sizeof(CParams), 0, cudaMemcpyDeviceToDevice, 0);
    agg_kernel<5, 64><<<524288 / 64, 64, smem5>>>(x, buf0);

    // level 1
    cudaMemcpyToSymbolAsync(cP, packp + 1, sizeof(CParams), 0, cudaMemcpyDeviceToDevice, 0);
    agg_kernel<1, 64><<<65536 / 64, 64, smem1>>>(buf0, buf1);

    // level 2
    cudaMemcpyToSymbolAsync(cP, packp + 2, sizeof(CParams), 0, cudaMemcpyDeviceToDevice, 0);
    agg_kernel<1, 64><<<8192 / 64, 64, smem1>>>(buf1, buf2);

    // level 3
    cudaMemcpyToSymbolAsync(cP, packp + 3, sizeof(CParams), 0, cudaMemcpyDeviceToDevice, 0);
    agg_kernel<1, 64><<<1024 / 64, 64, smem1>>>(buf2, out);
}